// round 3
// baseline (speedup 1.0000x reference)
#include <cuda_runtime.h>
#include <cuda_bf16.h>

#define VOCAB 50257
#define BATCH 512
#define SEQ   512

// One row per block, one token per thread. Warp-level reduce + one atomicAdd
// per warp per class. Bias folded in as bias/16 per warp (16 warps per row,
// power-of-two scale => exact). Output pre-zeroed by captured memset node.
__global__ __launch_bounds__(SEQ) void bow_logits_kernel(
    const int*   __restrict__ ids,
    const float* __restrict__ W,     // [2, VOCAB]
    const float* __restrict__ bias,  // [2]
    float*       __restrict__ out)   // [BATCH, 2], pre-zeroed
{
    const int row = blockIdx.x;
    const int tid = threadIdx.x;

    const int id = __ldg(ids + (row << 9) + tid);

    float s0 = 0.f, s1 = 0.f;
    if (id != 0) {
        // Two independent gathers, issued back-to-back (overlapped in LSU).
        s0 = __ldg(W + id);
        s1 = __ldg(W + VOCAB + id);
    }

    // Warp reduction.
    #pragma unroll
    for (int o = 16; o > 0; o >>= 1) {
        s0 += __shfl_down_sync(0xffffffffu, s0, o);
        s1 += __shfl_down_sync(0xffffffffu, s1, o);
    }

    if ((tid & 31) == 0) {
        // 16 warps per row; each contributes bias/16 so the total adds one bias.
        const float inv = 0.0625f;
        atomicAdd(out + row * 2 + 0, s0 + __ldg(bias + 0) * inv);
        atomicAdd(out + row * 2 + 1, s1 + __ldg(bias + 1) * inv);
    }
}

extern "C" void kernel_launch(void* const* d_in, const int* in_sizes, int n_in,
                              void* d_out, int out_size) {
    const int*   ids  = (const int*)  d_in[0];  // input_ids [512, 512] int32
    const float* W    = (const float*)d_in[1];  // W [2, 50257] fp32
    const float* bias = (const float*)d_in[2];  // b [2] fp32
    float*       out  = (float*)d_out;          // logits [512, 2] fp32

    cudaMemsetAsync(d_out, 0, (size_t)out_size * sizeof(float));
    bow_logits_kernel<<<BATCH, SEQ>>>(ids, W, bias, out);
}

// round 4
// speedup vs baseline: 1.3477x; 1.3477x over previous
#include <cuda_runtime.h>
#include <cuda_bf16.h>

#define VOCAB 50257
#define BATCH 512
#define SEQ   512
#define TPB   256   // 2 tokens per thread

// Interleaved weight table: one 8B gather per token instead of two 4B gathers.
__device__ float2 g_Wp[VOCAB];

__global__ __launch_bounds__(256) void interleave_W_kernel(const float* __restrict__ W) {
    // 2 vocab elements per thread -> 4 independent coalesced loads (MLP=4).
    const int i = blockIdx.x * 256 + threadIdx.x;
    const int v0 = i * 2, v1 = i * 2 + 1;
    if (v1 < VOCAB) {
        float a0 = __ldg(W + v0);
        float a1 = __ldg(W + v1);
        float b0 = __ldg(W + VOCAB + v0);
        float b1 = __ldg(W + VOCAB + v1);
        g_Wp[v0] = make_float2(a0, b0);
        g_Wp[v1] = make_float2(a1, b1);
    } else if (v0 < VOCAB) {
        g_Wp[v0] = make_float2(__ldg(W + v0), __ldg(W + VOCAB + v0));
    }
}

__global__ __launch_bounds__(TPB) void bow_logits_kernel(
    const int*   __restrict__ ids,
    const float* __restrict__ bias,
    float*       __restrict__ out)   // [BATCH, 2]
{
    const int row = blockIdx.x;
    const int tid = threadIdx.x;

    // 2 tokens per thread via one aligned 8B load.
    const int2 t2 = *reinterpret_cast<const int2*>(ids + (row << 9) + tid * 2);

    // Two independent 8B gathers, front-batched by ptxas.
    float2 w0 = (t2.x != 0) ? g_Wp[t2.x] : make_float2(0.f, 0.f);
    float2 w1 = (t2.y != 0) ? g_Wp[t2.y] : make_float2(0.f, 0.f);

    float s0 = w0.x + w1.x;
    float s1 = w0.y + w1.y;

    // Warp reduction.
    #pragma unroll
    for (int o = 16; o > 0; o >>= 1) {
        s0 += __shfl_down_sync(0xffffffffu, s0, o);
        s1 += __shfl_down_sync(0xffffffffu, s1, o);
    }

    __shared__ float2 sm[TPB / 32];
    const int w = tid >> 5, l = tid & 31;
    if (l == 0) sm[w] = make_float2(s0, s1);
    __syncthreads();

    if (tid == 0) {
        float r0 = 0.f, r1 = 0.f;
        #pragma unroll
        for (int i = 0; i < TPB / 32; i++) { r0 += sm[i].x; r1 += sm[i].y; }
        out[row * 2 + 0] = r0 + __ldg(bias + 0);
        out[row * 2 + 1] = r1 + __ldg(bias + 1);
    }
}

extern "C" void kernel_launch(void* const* d_in, const int* in_sizes, int n_in,
                              void* d_out, int out_size) {
    const int*   ids  = (const int*)  d_in[0];  // input_ids [512, 512] int32
    const float* W    = (const float*)d_in[1];  // W [2, 50257] fp32
    const float* bias = (const float*)d_in[2];  // b [2] fp32
    float*       out  = (float*)d_out;          // logits [512, 2] fp32

    interleave_W_kernel<<<(VOCAB / 2 + 255) / 256 + 1, 256>>>(W);
    bow_logits_kernel<<<BATCH, TPB>>>(ids, bias, out);
}